// round 9
// baseline (speedup 1.0000x reference)
#include <cuda_runtime.h>
#include <math.h>

// Problem constants (fixed by the dataset)
#define A_   16
#define SK_  2048
#define SQ_  2048
#define D_   128
#define IDM_ 128
#define RR_  3
// T_ANNEAL = 10, t_ANNEAL = 0

#define FOLD_BLOCKS 32
#define CODE_BLOCKS 8192          // 65536 rows, 8 warps x 1 row per block

// ---------------------------------------------------------------------------
// Scratch + gate (device globals — no allocation allowed)
// ---------------------------------------------------------------------------
__device__ float  g_M[2][A_ * IDM_ * RR_];   // folded projections
__device__ float  g_c[2][A_ * RR_];          // folded bias projections
__device__ float4 g_code[2][A_ * SK_];       // [0] = Kc/3, [1] = Qc
__device__ unsigned g_F;   // fold done count (0..32)
__device__ unsigned g_C;   // code done count; last code block resets both

__device__ __forceinline__ void spin_until(const unsigned* p, unsigned target) {
    while (__ldcg(p) < target) __nanosleep(32);
}

// ---------------------------------------------------------------------------
// Kernel A: fold (32 blocks) + code (8192 blocks, 1 row/warp as in R6).
// Code blocks issue their X loads BEFORE waiting on the fold gate, so the
// fold latency is hidden under the X DRAM reads for wave-1 blocks.
// ---------------------------------------------------------------------------
__global__ void __launch_bounds__(256) foldcode_kernel(
        const float* __restrict__ K,  const float* __restrict__ Q,
        const float* __restrict__ Wk, const float* __restrict__ bk,
        const float* __restrict__ Wq, const float* __restrict__ bq,
        const float* __restrict__ W) {
    const int bid = blockIdx.x;
    const int t   = threadIdx.x;

    if (bid < FOLD_BLOCKS) {
        // ----------------- FOLD: one block per (side, a) -------------------
        const int side = bid >> 4;
        const int a    = bid & 15;
        const float* Wx = side ? Wq : Wk;
        const float* bx = side ? bq : bk;

        __shared__ float Wsh[IDM_ * RR_];      // W[a] : [128,3]
        __shared__ float red[2][IDM_ * RR_];   // two 64-e halves

        for (int i = t; i < IDM_ * RR_; i += 256) Wsh[i] = W[a * IDM_ * RR_ + i];
        __syncthreads();

        {
            const int d = t & 127;
            const int h = t >> 7;              // half 0/1 -> 64 e's each
            float a0 = 0.f, a1 = 0.f, a2 = 0.f;
#pragma unroll 16
            for (int i = 0; i < 64; i++) {
                int e = h * 64 + i;
                float w = Wx[e * D_ + d];
                a0 = fmaf(w, Wsh[e * 3 + 0], a0);
                a1 = fmaf(w, Wsh[e * 3 + 1], a1);
                a2 = fmaf(w, Wsh[e * 3 + 2], a2);
            }
            red[h][d * 3 + 0] = a0;
            red[h][d * 3 + 1] = a1;
            red[h][d * 3 + 2] = a2;
        }
        __syncthreads();

        {
            int base = a * (IDM_ * RR_);
            for (int i = t; i < IDM_ * RR_; i += 256)
                g_M[side][base + i] = red[0][i] + red[1][i];
        }

        if (t < 32) {   // bias fold on warp 0
            float c0 = 0.f, c1 = 0.f, c2 = 0.f;
#pragma unroll
            for (int e = t; e < IDM_; e += 32) {
                float b = bx[e];
                c0 = fmaf(b, Wsh[e * 3 + 0], c0);
                c1 = fmaf(b, Wsh[e * 3 + 1], c1);
                c2 = fmaf(b, Wsh[e * 3 + 2], c2);
            }
#pragma unroll
            for (int o = 16; o > 0; o >>= 1) {
                c0 += __shfl_xor_sync(0xffffffffu, c0, o);
                c1 += __shfl_xor_sync(0xffffffffu, c1, o);
                c2 += __shfl_xor_sync(0xffffffffu, c2, o);
            }
            if (t == 0) {
                g_c[side][a * RR_ + 0] = c0;
                g_c[side][a * RR_ + 1] = c1;
                g_c[side][a * RR_ + 2] = c2;
            }
        }
        __syncthreads();
        if (t == 0) { __threadfence(); atomicAdd(&g_F, 1u); }

    } else {
        // ----------------- CODE: 8 warps, 1 row each (R6 layout) -----------
        int warp = (bid - FOLD_BLOCKS) * 8 + (t >> 5);
        int lane = t & 31;
        int which = (warp >= A_ * SK_) ? 1 : 0;
        int row   = which ? (warp - A_ * SK_) : warp;
        int a     = row >> 11;

        // Issue the X load FIRST — overlaps with the fold-gate wait.
        const float* X = which ? Q : K;
        const float4 x = reinterpret_cast<const float4*>(X)[row * (D_ / 4) + lane];

        // Gate: wait for fold results (short-range; fold blocks co-resident).
        if (t == 0) spin_until(&g_F, FOLD_BLOCKS);
        __syncthreads();
        __threadfence();   // acquire g_M / g_c

        const float* M = &g_M[which][a * (IDM_ * RR_) + lane * 12];
        float4 m0 = *reinterpret_cast<const float4*>(M);
        float4 m1 = *reinterpret_cast<const float4*>(M + 4);
        float4 m2 = *reinterpret_cast<const float4*>(M + 8);

        float p0 = x.x * m0.x + x.y * m0.w + x.z * m1.z + x.w * m2.y;
        float p1 = x.x * m0.y + x.y * m1.x + x.z * m1.w + x.w * m2.z;
        float p2 = x.x * m0.z + x.y * m1.y + x.z * m2.x + x.w * m2.w;

#pragma unroll
        for (int o = 16; o > 0; o >>= 1) {
            p0 += __shfl_xor_sync(0xffffffffu, p0, o);
            p1 += __shfl_xor_sync(0xffffffffu, p1, o);
            p2 += __shfl_xor_sync(0xffffffffu, p2, o);
        }
        if (lane == 0) {
            const float* c = &g_c[which][a * RR_];
            float scale = which ? 1.0f : (1.0f / 3.0f);   // fold /R into Kc
            float v0 = tanhf((p0 + c[0]) * 0.1f) * scale;
            float v1 = tanhf((p1 + c[1]) * 0.1f) * scale;
            float v2 = tanhf((p2 + c[2]) * 0.1f) * scale;
            g_code[which][row] = make_float4(v0, v1, v2, 0.f);
        }
        __syncthreads();
        if (t == 0) {
            unsigned c = atomicAdd(&g_C, 1u);
            if (c == CODE_BLOCKS - 1) {        // last code block resets gates
                g_F = 0;
                __threadfence();
                g_C = 0;
            }
        }
    }
}

// ---------------------------------------------------------------------------
// Kernel B (R6 version): main pass, 16 t-rows x 1024 s-cols per block.
// Kc direct LDG.128 (L2-hot); Qc via tiny smem; plain coalesced stores.
// ---------------------------------------------------------------------------
__device__ __forceinline__ float pc_fn(const float4 q, const float4 k) {
    float x  = fmaf(q.x, k.x, fmaf(q.y, k.y, q.z * k.z));      // Kc already /3
    float t  = x * x;
    float sg = fmaf(x, fmaf(t, -2.0833333e-5f, 0.025f), 0.5f); // sigmoid(x/10)
    return x * sg;
}

__global__ void __launch_bounds__(256) pc_kernel(float* __restrict__ out) {
    const int a     = blockIdx.z;
    const int tbase = blockIdx.y * 16;
    const int sbase = blockIdx.x * 1024;
    const int tid   = threadIdx.x;

    __shared__ float4 qc_sh[16];
    if (tid < 16)
        qc_sh[tid] = g_code[1][a * SQ_ + tbase + tid];

    const float4* kc = &g_code[0][a * SK_ + sbase + tid * 4];
    const float4 k0 = kc[0];
    const float4 k1 = kc[1];
    const float4 k2 = kc[2];
    const float4 k3 = kc[3];
    __syncthreads();

    size_t obase = ((size_t)(a * SQ_ + tbase)) * SK_ + (size_t)(sbase + tid * 4);
#pragma unroll
    for (int j = 0; j < 16; j++) {
        const float4 q = qc_sh[j];        // broadcast LDS
        float4 o;
        o.x = pc_fn(q, k0);
        o.y = pc_fn(q, k1);
        o.z = pc_fn(q, k2);
        o.w = pc_fn(q, k3);
        *reinterpret_cast<float4*>(out + obase + (size_t)j * SK_) = o;
    }
}

// ---------------------------------------------------------------------------
// Launch
// ---------------------------------------------------------------------------
extern "C" void kernel_launch(void* const* d_in, const int* in_sizes, int n_in,
                              void* d_out, int out_size) {
    const float* K  = (const float*)d_in[0];
    const float* Q  = (const float*)d_in[1];
    const float* Wk = (const float*)d_in[2];
    const float* bk = (const float*)d_in[3];
    const float* Wq = (const float*)d_in[4];
    const float* bq = (const float*)d_in[5];
    const float* W  = (const float*)d_in[6];
    float* out = (float*)d_out;

    foldcode_kernel<<<FOLD_BLOCKS + CODE_BLOCKS, 256>>>(K, Q, Wk, bk, Wq, bq, W);
    pc_kernel<<<dim3(SK_ / 1024, SQ_ / 16, A_), 256>>>(out);
}

// round 10
// speedup vs baseline: 1.3007x; 1.3007x over previous
#include <cuda_runtime.h>
#include <math.h>

// Problem constants (fixed by the dataset)
#define A_   16
#define SK_  2048
#define SQ_  2048
#define D_   128
#define IDM_ 128
#define RR_  3
// T_ANNEAL = 10, t_ANNEAL = 0

// ---------------------------------------------------------------------------
// Scratch (device globals — no allocation allowed)
// ---------------------------------------------------------------------------
__device__ float  g_M[2][A_ * IDM_ * RR_];   // folded projections
__device__ float  g_c[2][A_ * RR_];          // folded bias projections
__device__ float4 g_code[2][A_ * SK_];       // [0] = Kc/3, [1] = Qc

// ---------------------------------------------------------------------------
// Kernel 1: fold Wk/Wq + bias through W[a].
// Grid: 32 blocks = (side, a).  Block: 512 threads = (epart 0..3, d 0..127).
// All 32 Wx loads issued up-front (MLP=32) before the dependent smem phase.
// ---------------------------------------------------------------------------
__global__ void __launch_bounds__(512) prep_kernel(
        const float* __restrict__ Wk, const float* __restrict__ bk,
        const float* __restrict__ Wq, const float* __restrict__ bq,
        const float* __restrict__ W) {
    const int side = blockIdx.x >> 4;        // 0 = K, 1 = Q
    const int a    = blockIdx.x & 15;
    const float* Wx = side ? Wq : Wk;
    const float* bx = side ? bq : bk;

    const int t  = threadIdx.x;
    const int d  = t & 127;
    const int ep = t >> 7;                   // e-partition 0..3

    // Prefetch: 32 independent LDGs in flight before anything else.
    float w[32];
#pragma unroll
    for (int i = 0; i < 32; i++)
        w[i] = Wx[(ep * 32 + i) * D_ + d];

    __shared__ float Wsh[IDM_ * RR_];        // W[a] : [128,3]
    __shared__ float red[4][IDM_ * RR_];     // partial sums

    for (int i = t; i < IDM_ * RR_; i += 512) Wsh[i] = W[a * IDM_ * RR_ + i];
    __syncthreads();

    float a0 = 0.f, a1 = 0.f, a2 = 0.f;
#pragma unroll
    for (int i = 0; i < 32; i++) {
        int e = ep * 32 + i;
        a0 = fmaf(w[i], Wsh[e * 3 + 0], a0);
        a1 = fmaf(w[i], Wsh[e * 3 + 1], a1);
        a2 = fmaf(w[i], Wsh[e * 3 + 2], a2);
    }
    red[ep][d * 3 + 0] = a0;
    red[ep][d * 3 + 1] = a1;
    red[ep][d * 3 + 2] = a2;
    __syncthreads();

    if (ep == 0) {
        int base = a * (IDM_ * RR_) + d * RR_;
#pragma unroll
        for (int r = 0; r < RR_; r++) {
            int i = d * 3 + r;
            g_M[side][base + r] = red[0][i] + red[1][i] + red[2][i] + red[3][i];
        }
    }

    if (t < 32) {   // bias fold on warp 0
        float c0 = 0.f, c1 = 0.f, c2 = 0.f;
#pragma unroll
        for (int e = t; e < IDM_; e += 32) {
            float b = bx[e];
            c0 = fmaf(b, Wsh[e * 3 + 0], c0);
            c1 = fmaf(b, Wsh[e * 3 + 1], c1);
            c2 = fmaf(b, Wsh[e * 3 + 2], c2);
        }
#pragma unroll
        for (int o = 16; o > 0; o >>= 1) {
            c0 += __shfl_xor_sync(0xffffffffu, c0, o);
            c1 += __shfl_xor_sync(0xffffffffu, c1, o);
            c2 += __shfl_xor_sync(0xffffffffu, c2, o);
        }
        if (t == 0) {
            g_c[side][a * RR_ + 0] = c0;
            g_c[side][a * RR_ + 1] = c1;
            g_c[side][a * RR_ + 2] = c2;
        }
    }
}

// ---------------------------------------------------------------------------
// Kernel 2 (R6/R2 version, proven): hash codes, one warp per sequence row.
// ---------------------------------------------------------------------------
__global__ void code_kernel(const float* __restrict__ K, const float* __restrict__ Q) {
    int warp = (blockIdx.x * blockDim.x + threadIdx.x) >> 5;
    int lane = threadIdx.x & 31;
    int which = (warp >= A_ * SK_) ? 1 : 0;
    int row   = which ? (warp - A_ * SK_) : warp;
    int a     = row >> 11;

    const float* X = which ? Q : K;
    const float4 x = reinterpret_cast<const float4*>(X)[row * (D_ / 4) + lane];

    const float* M = &g_M[which][a * (IDM_ * RR_) + lane * 12];
    float4 m0 = *reinterpret_cast<const float4*>(M);
    float4 m1 = *reinterpret_cast<const float4*>(M + 4);
    float4 m2 = *reinterpret_cast<const float4*>(M + 8);

    float p0 = x.x * m0.x + x.y * m0.w + x.z * m1.z + x.w * m2.y;
    float p1 = x.x * m0.y + x.y * m1.x + x.z * m1.w + x.w * m2.z;
    float p2 = x.x * m0.z + x.y * m1.y + x.z * m2.x + x.w * m2.w;

#pragma unroll
    for (int o = 16; o > 0; o >>= 1) {
        p0 += __shfl_xor_sync(0xffffffffu, p0, o);
        p1 += __shfl_xor_sync(0xffffffffu, p1, o);
        p2 += __shfl_xor_sync(0xffffffffu, p2, o);
    }
    if (lane == 0) {
        const float* c = &g_c[which][a * RR_];
        float scale = which ? 1.0f : (1.0f / 3.0f);
        float v0 = tanhf((p0 + c[0]) * 0.1f) * scale;
        float v1 = tanhf((p1 + c[1]) * 0.1f) * scale;
        float v2 = tanhf((p2 + c[2]) * 0.1f) * scale;
        g_code[which][row] = make_float4(v0, v1, v2, 0.f);
    }
}

// ---------------------------------------------------------------------------
// Kernel 3: main pass, 16 t-rows x 1024 s-cols per 256-thread block.
// unroll 4 on the j-loop to cut register pressure (47 -> ~40) and raise occ.
// ---------------------------------------------------------------------------
__device__ __forceinline__ float pc_fn(const float4 q, const float4 k) {
    float x  = fmaf(q.x, k.x, fmaf(q.y, k.y, q.z * k.z));      // Kc already /3
    float t  = x * x;
    float sg = fmaf(x, fmaf(t, -2.0833333e-5f, 0.025f), 0.5f); // sigmoid(x/10)
    return x * sg;
}

__global__ void __launch_bounds__(256) pc_kernel(float* __restrict__ out) {
    const int a     = blockIdx.z;
    const int tbase = blockIdx.y * 16;
    const int sbase = blockIdx.x * 1024;
    const int tid   = threadIdx.x;

    __shared__ float4 qc_sh[16];
    if (tid < 16)
        qc_sh[tid] = g_code[1][a * SQ_ + tbase + tid];

    const float4* kc = &g_code[0][a * SK_ + sbase + tid * 4];
    const float4 k0 = kc[0];
    const float4 k1 = kc[1];
    const float4 k2 = kc[2];
    const float4 k3 = kc[3];
    __syncthreads();

    float* obase = out + ((size_t)(a * SQ_ + tbase)) * SK_ + (size_t)(sbase + tid * 4);
#pragma unroll 4
    for (int j = 0; j < 16; j++) {
        const float4 q = qc_sh[j];        // broadcast LDS
        float4 o;
        o.x = pc_fn(q, k0);
        o.y = pc_fn(q, k1);
        o.z = pc_fn(q, k2);
        o.w = pc_fn(q, k3);
        *reinterpret_cast<float4*>(obase + (size_t)j * SK_) = o;
    }
}

// ---------------------------------------------------------------------------
// Launch
// ---------------------------------------------------------------------------
extern "C" void kernel_launch(void* const* d_in, const int* in_sizes, int n_in,
                              void* d_out, int out_size) {
    const float* K  = (const float*)d_in[0];
    const float* Q  = (const float*)d_in[1];
    const float* Wk = (const float*)d_in[2];
    const float* bk = (const float*)d_in[3];
    const float* Wq = (const float*)d_in[4];
    const float* bq = (const float*)d_in[5];
    const float* W  = (const float*)d_in[6];
    float* out = (float*)d_out;

    prep_kernel<<<2 * A_, 512>>>(Wk, bk, Wq, bq, W);
    code_kernel<<<(2 * A_ * SK_) / 8, 256>>>(K, Q);
    pc_kernel<<<dim3(SK_ / 1024, SQ_ / 16, A_), 256>>>(out);
}